// round 15
// baseline (speedup 1.0000x reference)
#include <cuda_runtime.h>

#define NN 512
#define RR 16
#define HH 16
#define TI 4               // i-rows per warp (contraction)
#define JS 32              // j slices (partial buffers)
#define JPW (NN/JS)        // 16 j per slice
#define JCH 8              // j's per chunk
#define NCH (JPW/JCH)      // 2 chunks
#define BLK 256
#define GRID_AC ((NN/32)*JS)     // 512 blocks

// smearing constants (f32)
#define SM_START 0.006737946999085467f
#define SM_MSTEP ((1.0f - SM_START) * (1.0f/15.0f))
#define SM_SBETA (0.125f * (1.0f - SM_START))
#define SM_BETA  (1.0f / (SM_SBETA * SM_SBETA))
#define PI_OVER5 0.6283185307179586f

// scratch
__device__ float g_bkp [JS*NN*48];
__device__ float g_bqp [JS*NN*48];
__device__ float g_Sp  [JS*NN*48];
__device__ float g_S   [NN*48];
__device__ __align__(16) float g_y  [NN*16];     // MLP1 hidden
__device__ __align__(16) float g_lr [NN*1024];   // left(512)|right(512)
__device__ float g_bk2p[JS*NN*48];
__device__ float g_bq2p[JS*NN*48];

// ---------------------------------------------------------------------------
// In-place pair generation (unchanged)
// ---------------------------------------------------------------------------
__device__ __forceinline__ void gen_pair(const float* s_xi, const float* s_xj,
                                         int il, int jsl,
                                         float* s_SMS, float4 (*s_DF)[32],
                                         int w, int lane)
{
    const float dx = s_xi[il*3+0] - s_xj[jsl*3+0];
    const float dy = s_xi[il*3+1] - s_xj[jsl*3+1];
    const float dz = s_xi[il*3+2] - s_xj[jsl*3+2];
    const float nsq = fmaf(dx,dx, fmaf(dy,dy, fmaf(dz,dz, 1e-6f)));
    const float rin = rsqrtf(nsq);
    const float d   = nsq * rin;
    const float inv = rin * rin;
    s_DF[w][lane] = make_float4(dx*inv, dy*inv, dz*inv, 0.f);

    const float e   = __expf(-d);
    const float cut = (d < 5.0f) ? 0.5f*(__cosf(d*PI_OVER5) + 1.0f) : 0.0f;
    float* dst = s_SMS + (w*32 + lane)*20;
    #pragma unroll
    for (int rg = 0; rg < 4; rg++) {
        float u0 = e - (SM_START + SM_MSTEP*(float)(rg*4+0));
        float u1 = e - (SM_START + SM_MSTEP*(float)(rg*4+1));
        float u2 = e - (SM_START + SM_MSTEP*(float)(rg*4+2));
        float u3 = e - (SM_START + SM_MSTEP*(float)(rg*4+3));
        float4 v;
        v.x = cut * __expf(-SM_BETA*u0*u0);
        v.y = cut * __expf(-SM_BETA*u1*u1);
        v.z = cut * __expf(-SM_BETA*u2*u2);
        v.w = cut * __expf(-SM_BETA*u3*u3);
        *(float4*)(dst + rg*4) = v;
    }
}

// ---------------------------------------------------------------------------
// Phase A: first contraction, register-prefetched chunk staging.
// ---------------------------------------------------------------------------
__global__ __launch_bounds__(BLK, 3) void phaseA(const float* __restrict__ x,
                                                 const float* __restrict__ W)
{
    __shared__ float s_xi[96], s_xj[48];
    __shared__ __align__(16) float s_WT[2*JCH*16*20];     // 20KB
    __shared__ __align__(16) float s_SMS[JCH*32*20];      // 20KB
    __shared__ __align__(16) float4 s_DF[JCH][32];        // 4KB

    const int tid  = threadIdx.x;
    const int w    = tid >> 5;
    const int lane = tid & 31;
    const int igb  = blockIdx.x >> 5;
    const int js   = blockIdx.x & (JS-1);
    const int i0b  = igb*32;
    const int c    = lane & 15;
    const bool isQ = lane >= 16;

    if (tid < 96)            s_xi[tid]    = x[i0b*3 + tid];
    else if (tid < 144)      s_xj[tid-96] = x[js*JPW*3 + (tid-96)];

    const float4* srcK = (const float4*)(W);
    const float4* srcQ = (const float4*)(W + NN*RR*HH);
    float4 vk[2], vq[2];

    float accP[TI][3], accS[TI][3];
    #pragma unroll
    for (int t = 0; t < TI; t++)
        #pragma unroll
        for (int b = 0; b < 3; b++) { accP[t][b] = 0.f; accS[t][b] = 0.f; }

    {   // prefetch chunk 0 weights
        const int base = (js*JPW)*64;
        vk[0] = srcK[base + tid]; vk[1] = srcK[base + tid + 256];
        vq[0] = srcQ[base + tid]; vq[1] = srcQ[base + tid + 256];
    }
    __syncthreads();

    for (int ch = 0; ch < NCH; ch++) {
        if (ch) __syncthreads();
        {   // scatter-store prefetched weights transposed [jl][c][20]
            #pragma unroll
            for (int k = 0; k < 2; k++) {
                int idx = tid + k*256;
                int jl = idx >> 6, rem = idx & 63;
                int r = rem >> 2, c4 = (rem & 3) << 2;
                float* dk = &s_WT[(jl*16 + c4)*20 + r];
                dk[0] = vk[k].x; dk[20] = vk[k].y; dk[40] = vk[k].z; dk[60] = vk[k].w;
                float* dq = &s_WT[2560 + (jl*16 + c4)*20 + r];
                dq[0] = vq[k].x; dq[20] = vq[k].y; dq[40] = vq[k].z; dq[60] = vq[k].w;
            }
        }
        gen_pair(s_xi, s_xj, lane, ch*JCH + w, s_SMS, s_DF, w, lane);
        __syncthreads();

        if (ch + 1 < NCH) {   // prefetch next chunk during compute
            const int base = (js*JPW + (ch+1)*JCH)*64;
            vk[0] = srcK[base + tid]; vk[1] = srcK[base + tid + 256];
            vq[0] = srcQ[base + tid]; vq[1] = srcQ[base + tid + 256];
        }

        #pragma unroll 2
        for (int jl = 0; jl < JCH; jl++) {
            const float* wp = &s_WT[(isQ ? 2560 : 0) + (jl*16 + c)*20];
            float4 w0 = *(const float4*)(wp);
            float4 w1 = *(const float4*)(wp+4);
            float4 w2 = *(const float4*)(wp+8);
            float4 w3 = *(const float4*)(wp+12);
            const float* smb = &s_SMS[(jl*32 + (w<<2))*20];

            float P[TI];
            #pragma unroll
            for (int t = 0; t < TI; t++) {
                const float* sr = smb + t*20;
                float4 a0 = *(const float4*)(sr);
                float4 a1 = *(const float4*)(sr+4);
                float4 a2 = *(const float4*)(sr+8);
                float4 a3 = *(const float4*)(sr+12);
                float p;
                p = a0.x*w0.x;        p = fmaf(a0.y,w0.y,p);
                p = fmaf(a0.z,w0.z,p); p = fmaf(a0.w,w0.w,p);
                p = fmaf(a1.x,w1.x,p); p = fmaf(a1.y,w1.y,p);
                p = fmaf(a1.z,w1.z,p); p = fmaf(a1.w,w1.w,p);
                p = fmaf(a2.x,w2.x,p); p = fmaf(a2.y,w2.y,p);
                p = fmaf(a2.z,w2.z,p); p = fmaf(a2.w,w2.w,p);
                p = fmaf(a3.x,w3.x,p); p = fmaf(a3.y,w3.y,p);
                p = fmaf(a3.z,w3.z,p); p = fmaf(a3.w,w3.w,p);
                P[t] = p;
            }

            #pragma unroll
            for (int t = 0; t < TI; t++) {
                float4 df = s_DF[jl][(w<<2)+t];
                accP[t][0] = fmaf(P[t], df.x, accP[t][0]);
                accP[t][1] = fmaf(P[t], df.y, accP[t][1]);
                accP[t][2] = fmaf(P[t], df.z, accP[t][2]);
                if (!isQ) {
                    float sv = s_SMS[(jl*32 + (w<<2)+t)*20 + c];
                    accS[t][0] = fmaf(sv, df.x, accS[t][0]);
                    accS[t][1] = fmaf(sv, df.y, accS[t][1]);
                    accS[t][2] = fmaf(sv, df.z, accS[t][2]);
                }
            }
        }
    }

    const int i0 = i0b + w*TI;
    float* outp = isQ ? g_bqp : g_bkp;
    #pragma unroll
    for (int t = 0; t < TI; t++)
        #pragma unroll
        for (int b = 0; b < 3; b++)
            outp[(js*NN + (i0+t))*48 + c*3 + b] = accP[t][b];
    if (!isQ) {
        #pragma unroll
        for (int t = 0; t < TI; t++)
            #pragma unroll
            for (int b = 0; b < 3; b++)
                g_Sp[(js*NN + (i0+t))*48 + c*3 + b] = accS[t][b];  // c == r
    }
}

// ---------------------------------------------------------------------------
// Phase B1: merge partials + S, att outer, MLP1 hidden -> g_y (no W2).
// ---------------------------------------------------------------------------
__global__ __launch_bounds__(256) void phaseB1(const float* __restrict__ W1,
                                               const float* __restrict__ b1)
{
    const int i = blockIdx.x;
    const int tid = threadIdx.x;
    __shared__ __align__(16) float s_m[3][JS][48];        // 18KB
    __shared__ float s_bk[48], s_bq[48];
    __shared__ __align__(16) float s_att[256];

    #pragma unroll
    for (int k = 0; k < 5; k++) {
        int idx = tid + k*256;
        if (idx < 3*JS*12) {
            int v = idx / (JS*12), rem = idx % (JS*12);
            int js = rem / 12, f = rem % 12;
            const float4* src = (v == 0) ? (const float4*)g_bkp
                              : (v == 1) ? (const float4*)g_bqp
                                         : (const float4*)g_Sp;
            *(float4*)&s_m[v][js][f*4] = src[(js*NN + i)*12 + f];
        }
    }
    __syncthreads();

    if (tid < 144) {
        int v = tid / 48, e = tid % 48;
        float s = 0.f;
        #pragma unroll
        for (int js = 0; js < JS; js++) s += s_m[v][js][e];
        if (v == 0) s_bk[e] = s;
        else if (v == 1) s_bq[e] = s;
        else g_S[i*48 + e] = s;
    }
    __syncthreads();

    {
        int h = tid >> 4, g = tid & 15;
        s_att[tid] = s_bk[h*3+0]*s_bq[g*3+0] + s_bk[h*3+1]*s_bq[g*3+1]
                   + s_bk[h*3+2]*s_bq[g*3+2];
    }
    __syncthreads();

    {   // y[h] = silu(b1[h] + att·W1[h,:]) — thread (h,t) does k=16t..16t+15
        int h = tid >> 4, t = tid & 15;
        const float4* wr = (const float4*)(W1 + h*256 + t*16);
        float4 q0 = __ldg(wr), q1 = __ldg(wr+1), q2 = __ldg(wr+2), q3 = __ldg(wr+3);
        const float4* ar = (const float4*)s_att + t*4;
        float4 a0 = ar[0], a1 = ar[1], a2 = ar[2], a3 = ar[3];
        float p;
        p = a0.x*q0.x;         p = fmaf(a0.y,q0.y,p);
        p = fmaf(a0.z,q0.z,p); p = fmaf(a0.w,q0.w,p);
        p = fmaf(a1.x,q1.x,p); p = fmaf(a1.y,q1.y,p);
        p = fmaf(a1.z,q1.z,p); p = fmaf(a1.w,q1.w,p);
        p = fmaf(a2.x,q2.x,p); p = fmaf(a2.y,q2.y,p);
        p = fmaf(a2.z,q2.z,p); p = fmaf(a2.w,q2.w,p);
        p = fmaf(a3.x,q3.x,p); p = fmaf(a3.y,q3.y,p);
        p = fmaf(a3.z,q3.z,p); p = fmaf(a3.w,q3.w,p);
        #pragma unroll
        for (int m = 8; m >= 1; m >>= 1) p += __shfl_xor_sync(0xffffffffu, p, m, 16);
        if (t == 0) {
            float y = p + b1[h];
            g_y[i*16 + h] = y / (1.0f + __expf(-y));
        }
    }
}

// ---------------------------------------------------------------------------
// Phase B2: g_lr[i][m] = sum_o y[i][o] * W2[m][o].  Tiled GEMM:
// block = (i-tile 32, m-tile 128); thread owns one m and 16 i's.
// ---------------------------------------------------------------------------
__global__ __launch_bounds__(256) void phaseB2(const float* __restrict__ W2)
{
    __shared__ __align__(16) float s_y[32*16];

    const int tid = threadIdx.x;
    const int i0  = (blockIdx.x >> 3) * 32;
    const int m0  = (blockIdx.x & 7) * 128;

    if (tid < 128)
        ((float4*)s_y)[tid] = ((const float4*)(g_y + i0*16))[tid];
    __syncthreads();

    const int m  = m0 + (tid & 127);
    const int ih = (tid >> 7) * 16;
    const float4* wr = (const float4*)(W2 + m*16);
    float4 q0 = __ldg(wr), q1 = __ldg(wr+1), q2 = __ldg(wr+2), q3 = __ldg(wr+3);

    #pragma unroll
    for (int ii = 0; ii < 16; ii++) {
        const float4* yr = (const float4*)&s_y[(ih+ii)*16];
        float4 a0 = yr[0], a1 = yr[1], a2 = yr[2], a3 = yr[3];
        float a;
        a = a0.x*q0.x;         a = fmaf(a0.y,q0.y,a);
        a = fmaf(a0.z,q0.z,a); a = fmaf(a0.w,q0.w,a);
        a = fmaf(a1.x,q1.x,a); a = fmaf(a1.y,q1.y,a);
        a = fmaf(a1.z,q1.z,a); a = fmaf(a1.w,q1.w,a);
        a = fmaf(a2.x,q2.x,a); a = fmaf(a2.y,q2.y,a);
        a = fmaf(a2.z,q2.z,a); a = fmaf(a2.w,q2.w,a);
        a = fmaf(a3.x,q3.x,a); a = fmaf(a3.y,q3.y,a);
        a = fmaf(a3.z,q3.z,a); a = fmaf(a3.w,q3.w,a);
        g_lr[(i0+ih+ii)*1024 + m] = a;
    }
}

// ---------------------------------------------------------------------------
// Phase C: second contraction (right-stream), register-prefetched staging.
// ---------------------------------------------------------------------------
__global__ __launch_bounds__(BLK, 3) void phaseC(const float* __restrict__ x)
{
    __shared__ float s_xi[96], s_xj[48];
    __shared__ __align__(16) float s_RT[2*JCH*16*20];     // 20KB
    __shared__ __align__(16) float s_SMS[JCH*32*20];
    __shared__ __align__(16) float4 s_DF[JCH][32];

    const int tid  = threadIdx.x;
    const int w    = tid >> 5;
    const int lane = tid & 31;
    const int igb  = blockIdx.x >> 5;
    const int js   = blockIdx.x & (JS-1);
    const int i0b  = igb*32;
    const int c    = lane & 15;
    const bool isQ = lane >= 16;

    if (tid < 96)            s_xi[tid]    = x[i0b*3 + tid];
    else if (tid < 144)      s_xj[tid-96] = x[js*JPW*3 + (tid-96)];

    const float4* src = (const float4*)g_lr;
    float4 rv[4];

    float accP[TI][3];
    #pragma unroll
    for (int t = 0; t < TI; t++)
        #pragma unroll
        for (int b = 0; b < 3; b++) accP[t][b] = 0.f;

    {   // prefetch chunk 0
        const int j0 = js*JPW;
        #pragma unroll
        for (int k = 0; k < 4; k++) {
            int idx = tid + k*256;
            int jl = idx >> 7, n = idx & 127;
            rv[k] = src[(j0+jl)*256 + 128 + n];
        }
    }
    __syncthreads();

    for (int ch = 0; ch < NCH; ch++) {
        if (ch) __syncthreads();
        {   // scatter-store prefetched lr-right transposed
            #pragma unroll
            for (int k = 0; k < 4; k++) {
                int idx = tid + k*256;
                int jl = idx >> 7, n = idx & 127;
                int half = n >> 6, rem2 = n & 63;
                int r = rem2 >> 2, c4 = (rem2 & 3) << 2;
                float* d = &s_RT[((half*JCH + jl)*16 + c4)*20 + r];
                d[0] = rv[k].x; d[20] = rv[k].y; d[40] = rv[k].z; d[60] = rv[k].w;
            }
        }
        gen_pair(s_xi, s_xj, lane, ch*JCH + w, s_SMS, s_DF, w, lane);
        __syncthreads();

        if (ch + 1 < NCH) {
            const int j0 = js*JPW + (ch+1)*JCH;
            #pragma unroll
            for (int k = 0; k < 4; k++) {
                int idx = tid + k*256;
                int jl = idx >> 7, n = idx & 127;
                rv[k] = src[(j0+jl)*256 + 128 + n];
            }
        }

        #pragma unroll 4
        for (int jl = 0; jl < JCH; jl++) {
            const float* wp = &s_RT[(isQ ? 2560 : 0) + (jl*16 + c)*20];
            float4 w0 = *(const float4*)(wp);
            float4 w1 = *(const float4*)(wp+4);
            float4 w2 = *(const float4*)(wp+8);
            float4 w3 = *(const float4*)(wp+12);
            const float* smb = &s_SMS[(jl*32 + (w<<2))*20];

            float P[TI];
            #pragma unroll
            for (int t = 0; t < TI; t++) {
                const float* sr = smb + t*20;
                float4 a0 = *(const float4*)(sr);
                float4 a1 = *(const float4*)(sr+4);
                float4 a2 = *(const float4*)(sr+8);
                float4 a3 = *(const float4*)(sr+12);
                float p;
                p = a0.x*w0.x;        p = fmaf(a0.y,w0.y,p);
                p = fmaf(a0.z,w0.z,p); p = fmaf(a0.w,w0.w,p);
                p = fmaf(a1.x,w1.x,p); p = fmaf(a1.y,w1.y,p);
                p = fmaf(a1.z,w1.z,p); p = fmaf(a1.w,w1.w,p);
                p = fmaf(a2.x,w2.x,p); p = fmaf(a2.y,w2.y,p);
                p = fmaf(a2.z,w2.z,p); p = fmaf(a2.w,w2.w,p);
                p = fmaf(a3.x,w3.x,p); p = fmaf(a3.y,w3.y,p);
                p = fmaf(a3.z,w3.z,p); p = fmaf(a3.w,w3.w,p);
                P[t] = p;
            }

            #pragma unroll
            for (int t = 0; t < TI; t++) {
                float4 df = s_DF[jl][(w<<2)+t];
                accP[t][0] = fmaf(P[t], df.x, accP[t][0]);
                accP[t][1] = fmaf(P[t], df.y, accP[t][1]);
                accP[t][2] = fmaf(P[t], df.z, accP[t][2]);
            }
        }
    }

    const int i0 = i0b + w*TI;
    float* outp = isQ ? g_bq2p : g_bk2p;
    #pragma unroll
    for (int t = 0; t < TI; t++)
        #pragma unroll
        for (int b = 0; b < 3; b++)
            outp[(js*NN + (i0+t))*48 + c*3 + b] = accP[t][b];
}

// ---------------------------------------------------------------------------
// Phase D: staged merge + left⊗S (from smem), att outer, MLP2, output.
// ---------------------------------------------------------------------------
__global__ __launch_bounds__(256) void phaseD(const float* __restrict__ W3,
                                              const float* __restrict__ b3,
                                              const float* __restrict__ W4,
                                              const float* __restrict__ b4,
                                              float* __restrict__ out)
{
    const int i = blockIdx.x;
    const int tid = threadIdx.x;
    __shared__ __align__(16) float s_m[2][JS][48];        // 12KB
    __shared__ __align__(16) float s_L[512];              // left halves
    __shared__ float s_S[48];
    __shared__ float s_bk[48], s_bq[48];
    __shared__ __align__(16) float s_att[256];
    __shared__ float s_y[16];

    #pragma unroll
    for (int k = 0; k < 3; k++) {
        int idx = tid + k*256;
        if (idx < 2*JS*12) {
            int v = idx / (JS*12), rem = idx % (JS*12);
            int js = rem / 12, f = rem % 12;
            const float4* src = (v == 0) ? (const float4*)g_bk2p
                                         : (const float4*)g_bq2p;
            *(float4*)&s_m[v][js][f*4] = src[(js*NN + i)*12 + f];
        }
    }
    if (tid < 128) ((float4*)s_L)[tid] = ((const float4*)(g_lr + i*1024))[tid];
    else if (tid < 176) s_S[tid-128] = g_S[i*48 + (tid-128)];
    __syncthreads();

    if (tid < 96) {
        int v = tid / 48, e = tid % 48;
        int cc = e / 3, b = e % 3;
        float s = 0.f;
        #pragma unroll
        for (int js = 0; js < JS; js++) s += s_m[v][js][e];
        const float* lp = &s_L[(v ? 256 : 0) + cc];
        #pragma unroll
        for (int r = 0; r < 16; r++) s = fmaf(lp[r*16], s_S[r*3+b], s);
        if (v == 0) s_bk[e] = s; else s_bq[e] = s;
    }
    __syncthreads();

    {
        int h = tid >> 4, g = tid & 15;
        s_att[tid] = s_bk[h*3+0]*s_bq[g*3+0] + s_bk[h*3+1]*s_bq[g*3+1]
                   + s_bk[h*3+2]*s_bq[g*3+2];
    }
    __syncthreads();

    {   // y[h] = silu(b3[h] + att·W3[h,:]) — vectorized strip per thread
        int h = tid >> 4, t = tid & 15;
        const float4* wr = (const float4*)(W3 + h*256 + t*16);
        float4 q0 = __ldg(wr), q1 = __ldg(wr+1), q2 = __ldg(wr+2), q3 = __ldg(wr+3);
        const float4* ar = (const float4*)s_att + t*4;
        float4 a0 = ar[0], a1 = ar[1], a2 = ar[2], a3 = ar[3];
        float p;
        p = a0.x*q0.x;         p = fmaf(a0.y,q0.y,p);
        p = fmaf(a0.z,q0.z,p); p = fmaf(a0.w,q0.w,p);
        p = fmaf(a1.x,q1.x,p); p = fmaf(a1.y,q1.y,p);
        p = fmaf(a1.z,q1.z,p); p = fmaf(a1.w,q1.w,p);
        p = fmaf(a2.x,q2.x,p); p = fmaf(a2.y,q2.y,p);
        p = fmaf(a2.z,q2.z,p); p = fmaf(a2.w,q2.w,p);
        p = fmaf(a3.x,q3.x,p); p = fmaf(a3.y,q3.y,p);
        p = fmaf(a3.z,q3.z,p); p = fmaf(a3.w,q3.w,p);
        #pragma unroll
        for (int m = 8; m >= 1; m >>= 1) p += __shfl_xor_sync(0xffffffffu, p, m, 16);
        if (t == 0) {
            float y = p + b3[h];
            s_y[h] = y / (1.0f + __expf(-y));
        }
    }
    __syncthreads();

    if (tid == 0) {
        float a = b4[0];
        #pragma unroll
        for (int o = 0; o < 16; o++) a = fmaf(s_y[o], W4[o], a);
        out[i] = a;
    }
}

// ---------------------------------------------------------------------------
extern "C" void kernel_launch(void* const* d_in, const int* in_sizes, int n_in,
                              void* d_out, int out_size)
{
    const float* x  = (const float*)d_in[0];
    const float* W  = (const float*)d_in[1];
    const float* W1 = (const float*)d_in[2];
    const float* b1 = (const float*)d_in[3];
    const float* W2 = (const float*)d_in[4];
    const float* W3 = (const float*)d_in[5];
    const float* b3 = (const float*)d_in[6];
    const float* W4 = (const float*)d_in[7];
    const float* b4 = (const float*)d_in[8];
    float* out = (float*)d_out;

    phaseA <<<GRID_AC, BLK>>>(x, W);
    phaseB1<<<NN, 256>>>(W1, b1);
    phaseB2<<<128, 256>>>(W2);
    phaseC <<<GRID_AC, BLK>>>(x);
    phaseD <<<NN, 256>>>(W3, b3, W4, b4, out);
}

// round 16
// speedup vs baseline: 1.0377x; 1.0377x over previous
#include <cuda_runtime.h>

#define NN 512
#define RR 16
#define HH 16
#define TI 4               // i-rows per warp (phaseA)
#define JS 32              // j slices (partial buffers)
#define JPW (NN/JS)        // 16 j per slice
#define JCH 8              // j's per chunk
#define NCH (JPW/JCH)      // 2 chunks
#define BLK 256
#define GRID_AC ((NN/32)*JS)     // 512 blocks

// smearing constants (f32)
#define SM_START 0.006737946999085467f
#define SM_MSTEP ((1.0f - SM_START) * (1.0f/15.0f))
#define SM_SBETA (0.125f * (1.0f - SM_START))
#define SM_BETA  (1.0f / (SM_SBETA * SM_SBETA))
#define PI_OVER5 0.6283185307179586f

// scratch
__device__ float g_bkp [JS*NN*48];
__device__ float g_bqp [JS*NN*48];
__device__ float g_Sp  [JS*NN*48];
__device__ float g_S   [NN*48];
__device__ __align__(16) float g_y  [NN*16];     // MLP1 hidden
__device__ __align__(16) float g_lr [NN*1024];   // left(512)|right(512)
__device__ float g_bk2p[JS*NN*48];
__device__ float g_bq2p[JS*NN*48];

// ---------------------------------------------------------------------------
// In-place pair generation: thread (il=lane, j=chunk j0+w).
// ---------------------------------------------------------------------------
__device__ __forceinline__ void gen_pair(const float* s_xi, const float* s_xj,
                                         int il, int jsl,
                                         float* s_SMS, float4* s_DF,
                                         int w, int lane)
{
    const float dx = s_xi[il*3+0] - s_xj[jsl*3+0];
    const float dy = s_xi[il*3+1] - s_xj[jsl*3+1];
    const float dz = s_xi[il*3+2] - s_xj[jsl*3+2];
    const float nsq = fmaf(dx,dx, fmaf(dy,dy, fmaf(dz,dz, 1e-6f)));
    const float rin = rsqrtf(nsq);
    const float d   = nsq * rin;
    const float inv = rin * rin;
    s_DF[w*32 + lane] = make_float4(dx*inv, dy*inv, dz*inv, 0.f);

    const float e   = __expf(-d);
    const float cut = (d < 5.0f) ? 0.5f*(__cosf(d*PI_OVER5) + 1.0f) : 0.0f;
    float* dst = s_SMS + (w*32 + lane)*20;
    #pragma unroll
    for (int rg = 0; rg < 4; rg++) {
        float u0 = e - (SM_START + SM_MSTEP*(float)(rg*4+0));
        float u1 = e - (SM_START + SM_MSTEP*(float)(rg*4+1));
        float u2 = e - (SM_START + SM_MSTEP*(float)(rg*4+2));
        float u3 = e - (SM_START + SM_MSTEP*(float)(rg*4+3));
        float4 v;
        v.x = cut * __expf(-SM_BETA*u0*u0);
        v.y = cut * __expf(-SM_BETA*u1*u1);
        v.z = cut * __expf(-SM_BETA*u2*u2);
        v.w = cut * __expf(-SM_BETA*u3*u3);
        *(float4*)(dst + rg*4) = v;
    }
}

// ---------------------------------------------------------------------------
// Phase A: first contraction (lane=c mapping), register-prefetched staging,
// split-chain P dot products.
// ---------------------------------------------------------------------------
__global__ __launch_bounds__(BLK, 3) void phaseA(const float* __restrict__ x,
                                                 const float* __restrict__ W)
{
    __shared__ float s_xi[96], s_xj[48];
    __shared__ __align__(16) float s_WT[2*JCH*16*20];     // 20KB
    __shared__ __align__(16) float s_SMS[JCH*32*20];      // 20KB
    __shared__ __align__(16) float4 s_DF[JCH*32];         // 4KB

    const int tid  = threadIdx.x;
    const int w    = tid >> 5;
    const int lane = tid & 31;
    const int igb  = blockIdx.x >> 5;
    const int js   = blockIdx.x & (JS-1);
    const int i0b  = igb*32;
    const int c    = lane & 15;
    const bool isQ = lane >= 16;

    if (tid < 96)            s_xi[tid]    = x[i0b*3 + tid];
    else if (tid < 144)      s_xj[tid-96] = x[js*JPW*3 + (tid-96)];

    const float4* srcK = (const float4*)(W);
    const float4* srcQ = (const float4*)(W + NN*RR*HH);
    float4 vk[2], vq[2];

    float accP[TI][3], accS[TI][3];
    #pragma unroll
    for (int t = 0; t < TI; t++)
        #pragma unroll
        for (int b = 0; b < 3; b++) { accP[t][b] = 0.f; accS[t][b] = 0.f; }

    {
        const int base = (js*JPW)*64;
        vk[0] = srcK[base + tid]; vk[1] = srcK[base + tid + 256];
        vq[0] = srcQ[base + tid]; vq[1] = srcQ[base + tid + 256];
    }
    __syncthreads();

    for (int ch = 0; ch < NCH; ch++) {
        if (ch) __syncthreads();
        {
            #pragma unroll
            for (int k = 0; k < 2; k++) {
                int idx = tid + k*256;
                int jl = idx >> 6, rem = idx & 63;
                int r = rem >> 2, c4 = (rem & 3) << 2;
                float* dk = &s_WT[(jl*16 + c4)*20 + r];
                dk[0] = vk[k].x; dk[20] = vk[k].y; dk[40] = vk[k].z; dk[60] = vk[k].w;
                float* dq = &s_WT[2560 + (jl*16 + c4)*20 + r];
                dq[0] = vq[k].x; dq[20] = vq[k].y; dq[40] = vq[k].z; dq[60] = vq[k].w;
            }
        }
        gen_pair(s_xi, s_xj, lane, ch*JCH + w, s_SMS, s_DF, w, lane);
        __syncthreads();

        if (ch + 1 < NCH) {
            const int base = (js*JPW + (ch+1)*JCH)*64;
            vk[0] = srcK[base + tid]; vk[1] = srcK[base + tid + 256];
            vq[0] = srcQ[base + tid]; vq[1] = srcQ[base + tid + 256];
        }

        #pragma unroll 2
        for (int jl = 0; jl < JCH; jl++) {
            const float* wp = &s_WT[(isQ ? 2560 : 0) + (jl*16 + c)*20];
            float4 w0 = *(const float4*)(wp);
            float4 w1 = *(const float4*)(wp+4);
            float4 w2 = *(const float4*)(wp+8);
            float4 w3 = *(const float4*)(wp+12);
            const float* smb = &s_SMS[(jl*32 + (w<<2))*20];

            float P[TI];
            #pragma unroll
            for (int t = 0; t < TI; t++) {
                const float* sr = smb + t*20;
                float4 a0 = *(const float4*)(sr);
                float4 a1 = *(const float4*)(sr+4);
                float4 a2 = *(const float4*)(sr+8);
                float4 a3 = *(const float4*)(sr+12);
                float plo, phi;
                plo = a0.x*w0.x;           plo = fmaf(a0.y,w0.y,plo);
                plo = fmaf(a0.z,w0.z,plo); plo = fmaf(a0.w,w0.w,plo);
                plo = fmaf(a1.x,w1.x,plo); plo = fmaf(a1.y,w1.y,plo);
                plo = fmaf(a1.z,w1.z,plo); plo = fmaf(a1.w,w1.w,plo);
                phi = a2.x*w2.x;           phi = fmaf(a2.y,w2.y,phi);
                phi = fmaf(a2.z,w2.z,phi); phi = fmaf(a2.w,w2.w,phi);
                phi = fmaf(a3.x,w3.x,phi); phi = fmaf(a3.y,w3.y,phi);
                phi = fmaf(a3.z,w3.z,phi); phi = fmaf(a3.w,w3.w,phi);
                P[t] = plo + phi;
            }

            #pragma unroll
            for (int t = 0; t < TI; t++) {
                float4 df = s_DF[jl*32 + (w<<2)+t];
                accP[t][0] = fmaf(P[t], df.x, accP[t][0]);
                accP[t][1] = fmaf(P[t], df.y, accP[t][1]);
                accP[t][2] = fmaf(P[t], df.z, accP[t][2]);
                if (!isQ) {
                    float sv = s_SMS[(jl*32 + (w<<2)+t)*20 + c];
                    accS[t][0] = fmaf(sv, df.x, accS[t][0]);
                    accS[t][1] = fmaf(sv, df.y, accS[t][1]);
                    accS[t][2] = fmaf(sv, df.z, accS[t][2]);
                }
            }
        }
    }

    const int i0 = i0b + w*TI;
    float* outp = isQ ? g_bqp : g_bkp;
    #pragma unroll
    for (int t = 0; t < TI; t++)
        #pragma unroll
        for (int b = 0; b < 3; b++)
            outp[(js*NN + (i0+t))*48 + c*3 + b] = accP[t][b];
    if (!isQ) {
        #pragma unroll
        for (int t = 0; t < TI; t++)
            #pragma unroll
            for (int b = 0; b < 3; b++)
                g_Sp[(js*NN + (i0+t))*48 + c*3 + b] = accS[t][b];  // c == r
    }
}

// ---------------------------------------------------------------------------
// Phase B1: merge partials + S, att outer, MLP1 hidden -> g_y.
// ---------------------------------------------------------------------------
__global__ __launch_bounds__(256) void phaseB1(const float* __restrict__ W1,
                                               const float* __restrict__ b1)
{
    const int i = blockIdx.x;
    const int tid = threadIdx.x;
    __shared__ __align__(16) float s_m[3][JS][48];
    __shared__ float s_bk[48], s_bq[48];
    __shared__ __align__(16) float s_att[256];

    #pragma unroll
    for (int k = 0; k < 5; k++) {
        int idx = tid + k*256;
        if (idx < 3*JS*12) {
            int v = idx / (JS*12), rem = idx % (JS*12);
            int js = rem / 12, f = rem % 12;
            const float4* src = (v == 0) ? (const float4*)g_bkp
                              : (v == 1) ? (const float4*)g_bqp
                                         : (const float4*)g_Sp;
            *(float4*)&s_m[v][js][f*4] = src[(js*NN + i)*12 + f];
        }
    }
    __syncthreads();

    if (tid < 144) {
        int v = tid / 48, e = tid % 48;
        float s = 0.f;
        #pragma unroll
        for (int js = 0; js < JS; js++) s += s_m[v][js][e];
        if (v == 0) s_bk[e] = s;
        else if (v == 1) s_bq[e] = s;
        else g_S[i*48 + e] = s;
    }
    __syncthreads();

    {
        int h = tid >> 4, g = tid & 15;
        s_att[tid] = s_bk[h*3+0]*s_bq[g*3+0] + s_bk[h*3+1]*s_bq[g*3+1]
                   + s_bk[h*3+2]*s_bq[g*3+2];
    }
    __syncthreads();

    {
        int h = tid >> 4, t = tid & 15;
        const float4* wr = (const float4*)(W1 + h*256 + t*16);
        float4 q0 = __ldg(wr), q1 = __ldg(wr+1), q2 = __ldg(wr+2), q3 = __ldg(wr+3);
        const float4* ar = (const float4*)s_att + t*4;
        float4 a0 = ar[0], a1 = ar[1], a2 = ar[2], a3 = ar[3];
        float p;
        p = a0.x*q0.x;         p = fmaf(a0.y,q0.y,p);
        p = fmaf(a0.z,q0.z,p); p = fmaf(a0.w,q0.w,p);
        p = fmaf(a1.x,q1.x,p); p = fmaf(a1.y,q1.y,p);
        p = fmaf(a1.z,q1.z,p); p = fmaf(a1.w,q1.w,p);
        p = fmaf(a2.x,q2.x,p); p = fmaf(a2.y,q2.y,p);
        p = fmaf(a2.z,q2.z,p); p = fmaf(a2.w,q2.w,p);
        p = fmaf(a3.x,q3.x,p); p = fmaf(a3.y,q3.y,p);
        p = fmaf(a3.z,q3.z,p); p = fmaf(a3.w,q3.w,p);
        #pragma unroll
        for (int m = 8; m >= 1; m >>= 1) p += __shfl_xor_sync(0xffffffffu, p, m, 16);
        if (t == 0) {
            float y = p + b1[h];
            g_y[i*16 + h] = y / (1.0f + __expf(-y));
        }
    }
}

// ---------------------------------------------------------------------------
// Phase B2: g_lr = y @ W2^T, tiled.
// ---------------------------------------------------------------------------
__global__ __launch_bounds__(256) void phaseB2(const float* __restrict__ W2)
{
    __shared__ __align__(16) float s_y[32*16];

    const int tid = threadIdx.x;
    const int i0  = (blockIdx.x >> 3) * 32;
    const int m0  = (blockIdx.x & 7) * 128;

    if (tid < 128)
        ((float4*)s_y)[tid] = ((const float4*)(g_y + i0*16))[tid];
    __syncthreads();

    const int m  = m0 + (tid & 127);
    const int ih = (tid >> 7) * 16;
    const float4* wr = (const float4*)(W2 + m*16);
    float4 q0 = __ldg(wr), q1 = __ldg(wr+1), q2 = __ldg(wr+2), q3 = __ldg(wr+3);

    #pragma unroll
    for (int ii = 0; ii < 16; ii++) {
        const float4* yr = (const float4*)&s_y[(ih+ii)*16];
        float4 a0 = yr[0], a1 = yr[1], a2 = yr[2], a3 = yr[3];
        float a;
        a = a0.x*q0.x;         a = fmaf(a0.y,q0.y,a);
        a = fmaf(a0.z,q0.z,a); a = fmaf(a0.w,q0.w,a);
        a = fmaf(a1.x,q1.x,a); a = fmaf(a1.y,q1.y,a);
        a = fmaf(a1.z,q1.z,a); a = fmaf(a1.w,q1.w,a);
        a = fmaf(a2.x,q2.x,a); a = fmaf(a2.y,q2.y,a);
        a = fmaf(a2.z,q2.z,a); a = fmaf(a2.w,q2.w,a);
        a = fmaf(a3.x,q3.x,a); a = fmaf(a3.y,q3.y,a);
        a = fmaf(a3.z,q3.z,a); a = fmaf(a3.w,q3.w,a);
        g_lr[(i0+ih+ii)*1024 + m] = a;
    }
}

// ---------------------------------------------------------------------------
// Phase C: second contraction, LANE=I mapping.
// Warps 0-3: K path, warps 4-7: Q path; warp pair-id wp handles jl {wp, wp+4}
// per chunk. Lane = i. 48 accumulators per lane; smem reduction at end.
// ---------------------------------------------------------------------------
#define RED_STRIDE 52

__global__ __launch_bounds__(BLK, 2) void phaseC(const float* __restrict__ x)
{
    __shared__ float s_xi[96], s_xj[48];
    __shared__ __align__(16) float s_RT[2*JCH*16*20];          // 20KB
    __shared__ __align__(16) float s_pool[4*32*RED_STRIDE];    // 26KB: SMS+DF / red

    float* s_SMS = s_pool;                       // JCH*32*20 = 5120 floats
    float4* s_DF = (float4*)(s_pool + 5120);     // JCH*32 float4 = 1024 floats
    float* s_red = s_pool;                       // [4][32][RED_STRIDE] after loop

    const int tid  = threadIdx.x;
    const int w    = tid >> 5;
    const int lane = tid & 31;
    const int igb  = blockIdx.x >> 5;
    const int js   = blockIdx.x & (JS-1);
    const int i0b  = igb*32;
    const int wp   = w & 3;
    const bool isQ = w >= 4;

    if (tid < 96)            s_xi[tid]    = x[i0b*3 + tid];
    else if (tid < 144)      s_xj[tid-96] = x[js*JPW*3 + (tid-96)];

    const float4* src = (const float4*)g_lr;
    float4 rv[4];

    float acc0[16], acc1[16], acc2[16];
    #pragma unroll
    for (int c = 0; c < 16; c++) { acc0[c]=0.f; acc1[c]=0.f; acc2[c]=0.f; }

    {   // prefetch chunk 0 lr-right
        const int j0 = js*JPW;
        #pragma unroll
        for (int k = 0; k < 4; k++) {
            int idx = tid + k*256;
            int jl = idx >> 7, n = idx & 127;
            rv[k] = src[(j0+jl)*256 + 128 + n];
        }
    }
    __syncthreads();

    for (int ch = 0; ch < NCH; ch++) {
        if (ch) __syncthreads();
        {   // scatter-store prefetched lr-right transposed [half][jl][c][20]
            #pragma unroll
            for (int k = 0; k < 4; k++) {
                int idx = tid + k*256;
                int jl = idx >> 7, n = idx & 127;
                int half = n >> 6, rem2 = n & 63;
                int r = rem2 >> 2, c4 = (rem2 & 3) << 2;
                float* d = &s_RT[((half*JCH + jl)*16 + c4)*20 + r];
                d[0] = rv[k].x; d[20] = rv[k].y; d[40] = rv[k].z; d[60] = rv[k].w;
            }
        }
        gen_pair(s_xi, s_xj, lane, ch*JCH + w, s_SMS, s_DF, w, lane);
        __syncthreads();

        if (ch + 1 < NCH) {
            const int j0 = js*JPW + (ch+1)*JCH;
            #pragma unroll
            for (int k = 0; k < 4; k++) {
                int idx = tid + k*256;
                int jl = idx >> 7, n = idx & 127;
                rv[k] = src[(j0+jl)*256 + 128 + n];
            }
        }

        // this warp's two j's: jl = wp and wp+4
        #pragma unroll
        for (int q = 0; q < 2; q++) {
            const int jl = wp + q*4;
            const float* sp = &s_SMS[(jl*32 + lane)*20];    // lane-private, CF
            float4 m0 = *(const float4*)(sp);
            float4 m1 = *(const float4*)(sp+4);
            float4 m2 = *(const float4*)(sp+8);
            float4 m3 = *(const float4*)(sp+12);
            float4 df = s_DF[jl*32 + lane];
            const float* wb = &s_RT[(isQ ? 2560 : 0) + jl*16*20];

            #pragma unroll
            for (int c = 0; c < 16; c++) {
                const float* wr = wb + c*20;
                float4 w0 = *(const float4*)(wr);
                float4 w1 = *(const float4*)(wr+4);
                float4 w2 = *(const float4*)(wr+8);
                float4 w3 = *(const float4*)(wr+12);
                float plo, phi;
                plo = m0.x*w0.x;           plo = fmaf(m0.y,w0.y,plo);
                plo = fmaf(m0.z,w0.z,plo); plo = fmaf(m0.w,w0.w,plo);
                plo = fmaf(m1.x,w1.x,plo); plo = fmaf(m1.y,w1.y,plo);
                plo = fmaf(m1.z,w1.z,plo); plo = fmaf(m1.w,w1.w,plo);
                phi = m2.x*w2.x;           phi = fmaf(m2.y,w2.y,phi);
                phi = fmaf(m2.z,w2.z,phi); phi = fmaf(m2.w,w2.w,phi);
                phi = fmaf(m3.x,w3.x,phi); phi = fmaf(m3.y,w3.y,phi);
                phi = fmaf(m3.z,w3.z,phi); phi = fmaf(m3.w,w3.w,phi);
                float p = plo + phi;
                acc0[c] = fmaf(p, df.x, acc0[c]);
                acc1[c] = fmaf(p, df.y, acc1[c]);
                acc2[c] = fmaf(p, df.z, acc2[c]);
            }
        }
    }

    // ---- reduction across the 4 warps of each path ----
    // pass 1: K warps
    __syncthreads();
    if (!isQ) {
        float* d = &s_red[(wp*32 + lane)*RED_STRIDE];
        #pragma unroll
        for (int c = 0; c < 16; c++) {
            d[c*3+0] = acc0[c]; d[c*3+1] = acc1[c]; d[c*3+2] = acc2[c];
        }
    }
    __syncthreads();
    #pragma unroll
    for (int k = 0; k < 6; k++) {
        int idx = tid + k*256;      // 1536 = 32*48
        int i = idx / 48, e = idx % 48;
        float s = s_red[(0*32+i)*RED_STRIDE + e] + s_red[(1*32+i)*RED_STRIDE + e]
                + s_red[(2*32+i)*RED_STRIDE + e] + s_red[(3*32+i)*RED_STRIDE + e];
        g_bk2p[(js*NN + i0b + i)*48 + e] = s;
    }
    __syncthreads();
    // pass 2: Q warps
    if (isQ) {
        float* d = &s_red[(wp*32 + lane)*RED_STRIDE];
        #pragma unroll
        for (int c = 0; c < 16; c++) {
            d[c*3+0] = acc0[c]; d[c*3+1] = acc1[c]; d[c*3+2] = acc2[c];
        }
    }
    __syncthreads();
    #pragma unroll
    for (int k = 0; k < 6; k++) {
        int idx = tid + k*256;
        int i = idx / 48, e = idx % 48;
        float s = s_red[(0*32+i)*RED_STRIDE + e] + s_red[(1*32+i)*RED_STRIDE + e]
                + s_red[(2*32+i)*RED_STRIDE + e] + s_red[(3*32+i)*RED_STRIDE + e];
        g_bq2p[(js*NN + i0b + i)*48 + e] = s;
    }
}

// ---------------------------------------------------------------------------
// Phase D: staged merge + left⊗S (smem), att outer, MLP2, output.
// ---------------------------------------------------------------------------
__global__ __launch_bounds__(256) void phaseD(const float* __restrict__ W3,
                                              const float* __restrict__ b3,
                                              const float* __restrict__ W4,
                                              const float* __restrict__ b4,
                                              float* __restrict__ out)
{
    const int i = blockIdx.x;
    const int tid = threadIdx.x;
    __shared__ __align__(16) float s_m[2][JS][48];
    __shared__ __align__(16) float s_L[512];
    __shared__ float s_S[48];
    __shared__ float s_bk[48], s_bq[48];
    __shared__ __align__(16) float s_att[256];
    __shared__ float s_y[16];

    #pragma unroll
    for (int k = 0; k < 3; k++) {
        int idx = tid + k*256;
        if (idx < 2*JS*12) {
            int v = idx / (JS*12), rem = idx % (JS*12);
            int js = rem / 12, f = rem % 12;
            const float4* src = (v == 0) ? (const float4*)g_bk2p
                                         : (const float4*)g_bq2p;
            *(float4*)&s_m[v][js][f*4] = src[(js*NN + i)*12 + f];
        }
    }
    if (tid < 128) ((float4*)s_L)[tid] = ((const float4*)(g_lr + i*1024))[tid];
    else if (tid < 176) s_S[tid-128] = g_S[i*48 + (tid-128)];
    __syncthreads();

    if (tid < 96) {
        int v = tid / 48, e = tid % 48;
        int cc = e / 3, b = e % 3;
        float s = 0.f;
        #pragma unroll
        for (int js = 0; js < JS; js++) s += s_m[v][js][e];
        const float* lp = &s_L[(v ? 256 : 0) + cc];
        #pragma unroll
        for (int r = 0; r < 16; r++) s = fmaf(lp[r*16], s_S[r*3+b], s);
        if (v == 0) s_bk[e] = s; else s_bq[e] = s;
    }
    __syncthreads();

    {
        int h = tid >> 4, g = tid & 15;
        s_att[tid] = s_bk[h*3+0]*s_bq[g*3+0] + s_bk[h*3+1]*s_bq[g*3+1]
                   + s_bk[h*3+2]*s_bq[g*3+2];
    }
    __syncthreads();

    {
        int h = tid >> 4, t = tid & 15;
        const float4* wr = (const float4*)(W3 + h*256 + t*16);
        float4 q0 = __ldg(wr), q1 = __ldg(wr+1), q2 = __ldg(wr+2), q3 = __ldg(wr+3);
        const float4* ar = (const float4*)s_att + t*4;
        float4 a0 = ar[0], a1 = ar[1], a2 = ar[2], a3 = ar[3];
        float p;
        p = a0.x*q0.x;         p = fmaf(a0.y,q0.y,p);
        p = fmaf(a0.z,q0.z,p); p = fmaf(a0.w,q0.w,p);
        p = fmaf(a1.x,q1.x,p); p = fmaf(a1.y,q1.y,p);
        p = fmaf(a1.z,q1.z,p); p = fmaf(a1.w,q1.w,p);
        p = fmaf(a2.x,q2.x,p); p = fmaf(a2.y,q2.y,p);
        p = fmaf(a2.z,q2.z,p); p = fmaf(a2.w,q2.w,p);
        p = fmaf(a3.x,q3.x,p); p = fmaf(a3.y,q3.y,p);
        p = fmaf(a3.z,q3.z,p); p = fmaf(a3.w,q3.w,p);
        #pragma unroll
        for (int m = 8; m >= 1; m >>= 1) p += __shfl_xor_sync(0xffffffffu, p, m, 16);
        if (t == 0) {
            float y = p + b3[h];
            s_y[h] = y / (1.0f + __expf(-y));
        }
    }
    __syncthreads();

    if (tid == 0) {
        float a = b4[0];
        #pragma unroll
        for (int o = 0; o < 16; o++) a = fmaf(s_y[o], W4[o], a);
        out[i] = a;
    }
}

// ---------------------------------------------------------------------------
extern "C" void kernel_launch(void* const* d_in, const int* in_sizes, int n_in,
                              void* d_out, int out_size)
{
    const float* x  = (const float*)d_in[0];
    const float* W  = (const float*)d_in[1];
    const float* W1 = (const float*)d_in[2];
    const float* b1 = (const float*)d_in[3];
    const float* W2 = (const float*)d_in[4];
    const float* W3 = (const float*)d_in[5];
    const float* b3 = (const float*)d_in[6];
    const float* W4 = (const float*)d_in[7];
    const float* b4 = (const float*)d_in[8];
    float* out = (float*)d_out;

    phaseA <<<GRID_AC, BLK>>>(x, W);
    phaseB1<<<NN, 256>>>(W1, b1);
    phaseB2<<<128, 256>>>(W2);
    phaseC <<<GRID_AC, BLK>>>(x);
    phaseD <<<NN, 256>>>(W3, b3, W4, b4, out);
}